// round 1
// baseline (speedup 1.0000x reference)
#include <cuda_runtime.h>
#include <math.h>

// Problem dims (fixed by setup_inputs)
#define NB 8
#define NS 2048
#define DV 768
#define DA 512
#define NK 512
#define NR (NB*NS)            // 16384 rows (b,s)
#define LAM 0.3f

// Fused GEMM tiling
#define BM 128
#define BN 64
#define KT 16
#define NTHREADS 256
#define BLOCKS_PER_MOD ((NK/BN)*(NR/BM))   // 8*128 = 1024

// Scratch (allocation-free: __device__ globals)
__device__ float g_smoothV[NR*DV];          // smooth(feat_vision)
__device__ float g_smoothA[NR*DA];          // smooth(feat_audio)
__device__ float g_Mv[NK*DA];               // proto_vision @ proj_audio_to_vision
__device__ float g_Ma[NK*DV];               // proto_audio  @ proj_vision_to_audio
__device__ float g_partials[2*BLOCKS_PER_MOD];

// ---------------------------------------------------------------------------
// 3-tap temporal smoothing along S with edge truncation, float4 vectorized.
// which=1 -> g_smoothV, which=0 -> g_smoothA
// ---------------------------------------------------------------------------
__global__ void smooth_kernel(const float* __restrict__ f, int D, int which)
{
    float* __restrict__ out = which ? g_smoothV : g_smoothA;
    const float4* __restrict__ fv = reinterpret_cast<const float4*>(f);
    float4* __restrict__ ov = reinterpret_cast<float4*>(out);
    const int D4 = D >> 2;
    const long total = (long)NR * D4;
    const float inv3 = 1.0f / 3.0f;
    for (long i = (long)blockIdx.x*blockDim.x + threadIdx.x; i < total;
         i += (long)gridDim.x*blockDim.x) {
        long row = i / D4;
        int s = (int)(row % NS);
        float4 c = fv[i];
        float4 r;
        if (s == 0) {
            float4 n = fv[i + D4];
            r.x=(c.x+n.x)*0.5f; r.y=(c.y+n.y)*0.5f;
            r.z=(c.z+n.z)*0.5f; r.w=(c.w+n.w)*0.5f;
        } else if (s == NS-1) {
            float4 p = fv[i - D4];
            r.x=(c.x+p.x)*0.5f; r.y=(c.y+p.y)*0.5f;
            r.z=(c.z+p.z)*0.5f; r.w=(c.w+p.w)*0.5f;
        } else {
            float4 p = fv[i - D4];
            float4 n = fv[i + D4];
            r.x=(p.x+c.x+n.x)*inv3; r.y=(p.y+c.y+n.y)*inv3;
            r.z=(p.z+c.z+n.z)*inv3; r.w=(p.w+c.w+n.w)*inv3;
        }
        ov[i] = r;
    }
}

// ---------------------------------------------------------------------------
// Small GEMM: M = P @ W,  P:(NK,D) row-major, W:(D,C) row-major -> M:(NK,C)
// which=0 -> g_Mv (C=DA), which=1 -> g_Ma (C=DV)
// ---------------------------------------------------------------------------
__global__ void proto_proj_kernel(const float* __restrict__ P,
                                  const float* __restrict__ W,
                                  int D, int C, int which)
{
    float* __restrict__ Cout = which ? g_Ma : g_Mv;
    __shared__ float As[16][16];
    __shared__ float Ws[16][17];
    int tx = threadIdx.x, ty = threadIdx.y;
    int row = blockIdx.y*16 + ty;
    int col = blockIdx.x*16 + tx;
    float acc = 0.f;
    for (int d0 = 0; d0 < D; d0 += 16) {
        As[ty][tx] = P[row*D + d0 + tx];
        Ws[ty][tx] = W[(d0+ty)*C + col];
        __syncthreads();
        #pragma unroll
        for (int kk = 0; kk < 16; kk++) acc += As[ty][kk]*Ws[kk][tx];
        __syncthreads();
    }
    Cout[row*C + col] = acc;
}

// ---------------------------------------------------------------------------
// One pass of the fused GEMM: acc[r][c] += sum_d A[row0+r, d] * B[col0+c, d]
// A, B already offset to (row0, col0). Both row-major with inner dim D.
// ---------------------------------------------------------------------------
__device__ __forceinline__ void gemm_pass(
    const float* __restrict__ A, const float* __restrict__ Bp, int D,
    int tid, int tx, int ty,
    float (&As)[KT][BM], float (&Bs)[KT][BN], float (&acc)[8][4])
{
    for (int k0 = 0; k0 < D; k0 += KT) {
        // A tile: BM x KT = 2048 floats, 2 float4 per thread, stored transposed
        #pragma unroll
        for (int r = 0; r < 2; r++) {
            int idx = r*1024 + tid*4;
            int row = idx / KT;
            int kk  = idx % KT;
            float4 v = *reinterpret_cast<const float4*>(A + (long)row*D + k0 + kk);
            As[kk+0][row] = v.x; As[kk+1][row] = v.y;
            As[kk+2][row] = v.z; As[kk+3][row] = v.w;
        }
        // B tile: BN x KT = 1024 floats, 1 float4 per thread
        {
            int idx = tid*4;
            int row = idx / KT;
            int kk  = idx % KT;
            float4 v = *reinterpret_cast<const float4*>(Bp + (long)row*D + k0 + kk);
            Bs[kk+0][row] = v.x; Bs[kk+1][row] = v.y;
            Bs[kk+2][row] = v.z; Bs[kk+3][row] = v.w;
        }
        __syncthreads();
        #pragma unroll
        for (int kk = 0; kk < KT; kk++) {
            float4 a0 = *reinterpret_cast<const float4*>(&As[kk][ty*8]);
            float4 a1 = *reinterpret_cast<const float4*>(&As[kk][ty*8+4]);
            float4 bv = *reinterpret_cast<const float4*>(&Bs[kk][tx*4]);
            float a[8] = {a0.x,a0.y,a0.z,a0.w,a1.x,a1.y,a1.z,a1.w};
            float b[4] = {bv.x,bv.y,bv.z,bv.w};
            #pragma unroll
            for (int i = 0; i < 8; i++)
                #pragma unroll
                for (int j = 0; j < 4; j++)
                    acc[i][j] += a[i]*b[j];
        }
        __syncthreads();
    }
}

// ---------------------------------------------------------------------------
// Fused: intra GEMM + cross GEMM + softplus epilogue + block reduce.
// modality 0: vision energy (A2=g_smoothA, B2=g_Mv, D2=DA)
// modality 1: audio  energy (A2=g_smoothV, B2=g_Ma, D2=DV)
// ---------------------------------------------------------------------------
__global__ __launch_bounds__(NTHREADS, 2)
void fused_energy_kernel(const float* __restrict__ feat,
                         const float* __restrict__ proto,
                         int D1, int modality)
{
    __shared__ float As[KT][BM];
    __shared__ float Bs[KT][BN];
    __shared__ float red[NTHREADS];

    const float* A2; const float* B2; int D2;
    if (modality == 0) { A2 = g_smoothA; B2 = g_Mv; D2 = DA; }
    else               { A2 = g_smoothV; B2 = g_Ma; D2 = DV; }

    const int tid = threadIdx.x;
    const int tx = tid & 15;      // col group: cols tx*4 .. tx*4+3
    const int ty = tid >> 4;      // row group: rows ty*8 .. ty*8+7
    const long row0 = (long)blockIdx.y * BM;
    const long col0 = (long)blockIdx.x * BN;

    float acc1[8][4], acc2[8][4];
    #pragma unroll
    for (int i = 0; i < 8; i++)
        #pragma unroll
        for (int j = 0; j < 4; j++) { acc1[i][j] = 0.f; acc2[i][j] = 0.f; }

    // intra = feat @ proto^T
    gemm_pass(feat + row0*D1, proto + col0*D1, D1, tid, tx, ty, As, Bs, acc1);
    // cross = smooth(comp) @ M^T
    gemm_pass(A2 + row0*D2, B2 + col0*D2, D2, tid, tx, ty, As, Bs, acc2);

    float local = 0.f;
    #pragma unroll
    for (int i = 0; i < 8; i++)
        #pragma unroll
        for (int j = 0; j < 4; j++) {
            float c1 = acc1[i][j];
            float c2 = acc2[i][j];
            float sal = LAM*c2*c2 + (1.0f - LAM)*c1*c1;
            float x = sal * c1;
            // stable softplus: max(x,0) + log1p(exp(-|x|))
            float sp = fmaxf(x, 0.f) + log1pf(expf(-fabsf(x)));
            local += sp;
        }

    red[tid] = local;
    __syncthreads();
    #pragma unroll
    for (int st = NTHREADS/2; st > 0; st >>= 1) {
        if (tid < st) red[tid] += red[tid + st];
        __syncthreads();
    }
    if (tid == 0) {
        int bidx = modality*BLOCKS_PER_MOD + blockIdx.y*gridDim.x + blockIdx.x;
        g_partials[bidx] = red[0];
    }
}

// ---------------------------------------------------------------------------
// Deterministic final reduction (fixed order, double accumulation)
// ---------------------------------------------------------------------------
__global__ void final_reduce_kernel(float* __restrict__ out)
{
    __shared__ double red[256];
    double s = 0.0;
    for (int i = threadIdx.x; i < 2*BLOCKS_PER_MOD; i += 256)
        s += (double)g_partials[i];
    red[threadIdx.x] = s;
    __syncthreads();
    for (int st = 128; st > 0; st >>= 1) {
        if (threadIdx.x < st) red[threadIdx.x] += red[threadIdx.x + st];
        __syncthreads();
    }
    if (threadIdx.x == 0) out[0] = (float)(-red[0]);
}

// ---------------------------------------------------------------------------
extern "C" void kernel_launch(void* const* d_in, const int* in_sizes, int n_in,
                              void* d_out, int out_size)
{
    const float* fv  = (const float*)d_in[0];   // (8,2048,768)
    const float* fa  = (const float*)d_in[1];   // (8,2048,512)
    const float* pv  = (const float*)d_in[2];   // (512,768)
    const float* pa  = (const float*)d_in[3];   // (512,512)
    const float* wav = (const float*)d_in[4];   // (768,512)  proj_audio_to_vision
    const float* wva = (const float*)d_in[5];   // (512,768)  proj_vision_to_audio
    float* out = (float*)d_out;

    smooth_kernel<<<4096, 256>>>(fv, DV, 1);    // -> g_smoothV
    smooth_kernel<<<4096, 256>>>(fa, DA, 0);    // -> g_smoothA

    // M_v = proto_vision @ proj_audio_to_vision : (512,768)x(768,512)->(512,512)
    proto_proj_kernel<<<dim3(DA/16, NK/16), dim3(16,16)>>>(pv, wav, DV, DA, 0);
    // M_a = proto_audio @ proj_vision_to_audio : (512,512)x(512,768)->(512,768)
    proto_proj_kernel<<<dim3(DV/16, NK/16), dim3(16,16)>>>(pa, wva, DA, DV, 1);

    dim3 grid(NK/BN, NR/BM);                    // (8, 128)
    fused_energy_kernel<<<grid, NTHREADS>>>(fv, pv, DV, 0);  // vision energy
    fused_energy_kernel<<<grid, NTHREADS>>>(fa, pa, DA, 1);  // audio energy

    final_reduce_kernel<<<1, 256>>>(out);
}

// round 5
// speedup vs baseline: 1.7324x; 1.7324x over previous
#include <cuda_runtime.h>
#include <cuda_bf16.h>
#include <math.h>
#include <stdint.h>

// Problem dims (fixed by setup_inputs)
#define NB 8
#define NS 2048
#define DV 768
#define DA 512
#define NK 512
#define NR (NB*NS)            // 16384 rows
#define LAM 0.3f

// Fused GEMM tiling (mma.sync m16n8k16 bf16)
#define BM 128
#define BN 128
#define BK 32                 // k per chunk
#define NTH 256
#define LDSE 40               // smem row stride in bf16 elements (80 bytes)
#define TILEB (128*LDSE*2)    // 10240 bytes per tile
#define NBLOCKS ((NK/BN)*(NR/BM)*2)   // 4*128*2 = 1024

// ---------------- device scratch (allocation-free), fp32 as in R1 ----------
__device__ float g_smoothV[(size_t)NR*DV];   // smooth(feat_vision)
__device__ float g_smoothA[(size_t)NR*DA];   // smooth(feat_audio)
__device__ float g_Mv[NK*DA];                // proto_vision @ proj_audio_to_vision
__device__ float g_Ma[NK*DV];                // proto_audio  @ proj_vision_to_audio
__device__ float g_partials[NBLOCKS];

// ---------------- helpers ----------------
__device__ __forceinline__ void mma16816(float* c, const uint32_t* a, const uint32_t* b) {
    asm volatile(
        "mma.sync.aligned.m16n8k16.row.col.f32.bf16.bf16.f32 "
        "{%0,%1,%2,%3}, {%4,%5,%6,%7}, {%8,%9}, {%0,%1,%2,%3};"
        : "+f"(c[0]), "+f"(c[1]), "+f"(c[2]), "+f"(c[3])
        : "r"(a[0]), "r"(a[1]), "r"(a[2]), "r"(a[3]), "r"(b[0]), "r"(b[1]));
}
__device__ __forceinline__ uint2 cvt4(float4 v) {
    __nv_bfloat162 lo = __floats2bfloat162_rn(v.x, v.y);
    __nv_bfloat162 hi = __floats2bfloat162_rn(v.z, v.w);
    uint2 r;
    r.x = *reinterpret_cast<uint32_t*>(&lo);
    r.y = *reinterpret_cast<uint32_t*>(&hi);
    return r;
}

// ---------------------------------------------------------------------------
// R1-VALIDATED: 3-tap temporal smoothing (fp32), edge truncation.
// which=1 -> g_smoothV, which=0 -> g_smoothA
// ---------------------------------------------------------------------------
__global__ void smooth_kernel(const float* __restrict__ f, int D, int which)
{
    float* __restrict__ out = which ? g_smoothV : g_smoothA;
    const float4* __restrict__ fv = reinterpret_cast<const float4*>(f);
    float4* __restrict__ ov = reinterpret_cast<float4*>(out);
    const int D4 = D >> 2;
    const long total = (long)NR * D4;
    const float inv3 = 1.0f / 3.0f;
    for (long i = (long)blockIdx.x*blockDim.x + threadIdx.x; i < total;
         i += (long)gridDim.x*blockDim.x) {
        long row = i / D4;
        int s = (int)(row % NS);
        float4 c = fv[i];
        float4 r;
        if (s == 0) {
            float4 n = fv[i + D4];
            r.x=(c.x+n.x)*0.5f; r.y=(c.y+n.y)*0.5f;
            r.z=(c.z+n.z)*0.5f; r.w=(c.w+n.w)*0.5f;
        } else if (s == NS-1) {
            float4 p = fv[i - D4];
            r.x=(c.x+p.x)*0.5f; r.y=(c.y+p.y)*0.5f;
            r.z=(c.z+p.z)*0.5f; r.w=(c.w+p.w)*0.5f;
        } else {
            float4 p = fv[i - D4];
            float4 n = fv[i + D4];
            r.x=(p.x+c.x+n.x)*inv3; r.y=(p.y+c.y+n.y)*inv3;
            r.z=(p.z+c.z+n.z)*inv3; r.w=(p.w+c.w+n.w)*inv3;
        }
        ov[i] = r;
    }
}

// ---------------------------------------------------------------------------
// R1-VALIDATED: M = P @ W (fp32), 16x16 tiles.
// which=0 -> g_Mv (C=DA), which=1 -> g_Ma (C=DV)
// ---------------------------------------------------------------------------
__global__ void proto_proj_kernel(const float* __restrict__ P,
                                  const float* __restrict__ W,
                                  int D, int C, int which)
{
    float* __restrict__ Cout = which ? g_Ma : g_Mv;
    __shared__ float As[16][16];
    __shared__ float Ws[16][17];
    int tx = threadIdx.x, ty = threadIdx.y;
    int row = blockIdx.y*16 + ty;
    int col = blockIdx.x*16 + tx;
    float acc = 0.f;
    for (int d0 = 0; d0 < D; d0 += 16) {
        As[ty][tx] = P[row*D + d0 + tx];
        Ws[ty][tx] = W[(d0+ty)*C + col];
        __syncthreads();
        #pragma unroll
        for (int kk = 0; kk < 16; kk++) acc += As[ty][kk]*Ws[kk][tx];
        __syncthreads();
    }
    Cout[row*C + col] = acc;
}

// ---------------------------------------------------------------------------
// Fused HMMA energy kernel. gridDim = (NK/BN, NR/BM, 2 modalities).
// Reads fp32 sources (harness inputs + R1-validated fp32 scratch), converts
// to bf16 in registers, stages to smem, HMMA core identical to R4.
// ---------------------------------------------------------------------------
__global__ __launch_bounds__(NTH, 1)
void fused_energy_kernel(const float* __restrict__ fv, const float* __restrict__ fa,
                         const float* __restrict__ pv, const float* __restrict__ pa)
{
    __shared__ __align__(16) __nv_bfloat16 smem[2][2][128*LDSE];  // 40 KB
    __shared__ float red_s[8];

    const int tid = threadIdx.x;
    const int wid = tid >> 5;
    const int lane = tid & 31;
    const int z = blockIdx.z;
    const long row0 = (long)blockIdx.y * BM;
    const long col0 = (long)blockIdx.x * BN;

    const float *A1, *B1, *A2, *B2;
    int D1, D2;
    if (z == 0) { A1 = fv; B1 = pv; D1 = DV; A2 = g_smoothA; B2 = g_Mv; D2 = DA; }
    else        { A1 = fa; B1 = pa; D1 = DA; A2 = g_smoothV; B2 = g_Ma; D2 = DV; }
    const int n1 = D1 / BK;
    const int nch = n1 + D2 / BK;

    // fetch chunk c: fp32 load + bf16 convert into registers (8 uint2)
    auto fetch = [&](int c, uint2 (&st)[8]) {
        const float *A, *B; int D, k0;
        if (c < n1) { A = A1; B = B1; D = D1; k0 = c * BK; }
        else        { A = A2; B = B2; D = D2; k0 = (c - n1) * BK; }
        #pragma unroll
        for (int r = 0; r < 4; r++) {
            int u = tid + r * 256;            // 1024 4-float units per matrix
            int row = u >> 3, seg = u & 7;
            float4 va = *reinterpret_cast<const float4*>(A + (row0 + row) * (long)D + k0 + seg * 4);
            st[r] = cvt4(va);
            float4 vb = *reinterpret_cast<const float4*>(B + (col0 + row) * (long)D + k0 + seg * 4);
            st[4 + r] = cvt4(vb);
        }
    };
    auto store = [&](int buf, const uint2 (&st)[8]) {
        char* base = reinterpret_cast<char*>(&smem[buf][0][0]);
        #pragma unroll
        for (int r = 0; r < 4; r++) {
            int u = tid + r * 256;
            int row = u >> 3, seg = u & 7;
            *reinterpret_cast<uint2*>(base + row * 80 + seg * 8) = st[r];
            *reinterpret_cast<uint2*>(base + TILEB + row * 80 + seg * 8) = st[4 + r];
        }
    };

    const int wm = (wid >> 2) * 64;   // warp row base
    const int wn = (wid & 3) * 32;    // warp col base
    const int g  = lane >> 2;         // fragment group row 0..7
    const int t2 = (lane & 3) * 2;    // fragment k pair base

    // direct fragment loads per PTX ISA mma.m16n8k16 tables
    auto compute_chunk = [&](int buf, float (*acc)[4][4]) {
        const __nv_bfloat16* S  = &smem[buf][0][0];
        const __nv_bfloat16* SB = &smem[buf][1][0];
        #pragma unroll
        for (int ks = 0; ks < 2; ks++) {
            const int kb = ks * 16 + t2;
            uint32_t a[4][4];
            #pragma unroll
            for (int i = 0; i < 4; i++) {
                const uint32_t* p0 = reinterpret_cast<const uint32_t*>(S + (wm + i*16 + g) * LDSE + kb);
                const uint32_t* p1 = reinterpret_cast<const uint32_t*>(S + (wm + i*16 + g + 8) * LDSE + kb);
                a[i][0] = p0[0];
                a[i][1] = p1[0];
                a[i][2] = p0[4];
                a[i][3] = p1[4];
            }
            uint32_t b[4][2];
            #pragma unroll
            for (int j = 0; j < 4; j++) {
                const uint32_t* pb = reinterpret_cast<const uint32_t*>(SB + (wn + j*8 + g) * LDSE + kb);
                b[j][0] = pb[0];
                b[j][1] = pb[4];
            }
            #pragma unroll
            for (int i = 0; i < 4; i++)
                #pragma unroll
                for (int j = 0; j < 4; j++)
                    mma16816(acc[i][j], a[i], b[j]);
        }
    };

    float acc1[4][4][4] = {};
    float acc2[4][4][4] = {};

    {
        uint2 st0[8];
        fetch(0, st0);
        store(0, st0);
    }
    __syncthreads();

    for (int c = 0; c < nch; c++) {
        uint2 stn[8];
        if (c + 1 < nch) fetch(c + 1, stn);         // LDG+CVT overlapped with compute
        compute_chunk(c & 1, (c < n1) ? acc1 : acc2);
        __syncthreads();                            // all reads of tile c done
        if (c + 1 < nch) store((c + 1) & 1, stn);
        __syncthreads();                            // tile c+1 visible
    }

    // Epilogue: elementwise softplus on matching fragments, then reduce.
    float local = 0.f;
    #pragma unroll
    for (int i = 0; i < 4; i++)
        #pragma unroll
        for (int j = 0; j < 4; j++)
            #pragma unroll
            for (int r = 0; r < 4; r++) {
                float c1 = acc1[i][j][r];
                float c2 = acc2[i][j][r];
                float sal = LAM * c2 * c2 + (1.0f - LAM) * c1 * c1;
                float x = sal * c1;
                local += fmaxf(x, 0.f) + log1pf(__expf(-fabsf(x)));
            }
    #pragma unroll
    for (int o = 16; o > 0; o >>= 1)
        local += __shfl_xor_sync(0xFFFFFFFF, local, o);
    if (lane == 0) red_s[wid] = local;
    __syncthreads();
    if (tid == 0) {
        float s = 0.f;
        #pragma unroll
        for (int w = 0; w < 8; w++) s += red_s[w];
        g_partials[(z * gridDim.y + blockIdx.y) * gridDim.x + blockIdx.x] = s;
    }
}

// ---------------------------------------------------------------------------
// Deterministic final reduction
// ---------------------------------------------------------------------------
__global__ void final_reduce_kernel(float* __restrict__ out)
{
    __shared__ double red[256];
    double s = 0.0;
    for (int i = threadIdx.x; i < NBLOCKS; i += 256) s += (double)g_partials[i];
    red[threadIdx.x] = s;
    __syncthreads();
    for (int st = 128; st > 0; st >>= 1) {
        if (threadIdx.x < st) red[threadIdx.x] += red[threadIdx.x + st];
        __syncthreads();
    }
    if (threadIdx.x == 0) out[0] = (float)(-red[0]);
}

// ---------------------------------------------------------------------------
extern "C" void kernel_launch(void* const* d_in, const int* in_sizes, int n_in,
                              void* d_out, int out_size)
{
    const float* fv  = (const float*)d_in[0];   // (8,2048,768)
    const float* fa  = (const float*)d_in[1];   // (8,2048,512)
    const float* pv  = (const float*)d_in[2];   // (512,768)
    const float* pa  = (const float*)d_in[3];   // (512,512)
    const float* wav = (const float*)d_in[4];   // (768,512)
    const float* wva = (const float*)d_in[5];   // (512,768)
    float* out = (float*)d_out;

    smooth_kernel<<<4096, 256>>>(fv, DV, 1);    // -> g_smoothV (fp32, R1-validated)
    smooth_kernel<<<4096, 256>>>(fa, DA, 0);    // -> g_smoothA

    proto_proj_kernel<<<dim3(DA/16, NK/16), dim3(16,16)>>>(pv, wav, DV, DA, 0);  // g_Mv
    proto_proj_kernel<<<dim3(DV/16, NK/16), dim3(16,16)>>>(pa, wva, DA, DV, 1);  // g_Ma

    fused_energy_kernel<<<dim3(NK/BN, NR/BM, 2), NTH>>>(fv, fa, pv, pa);

    final_reduce_kernel<<<1, 256>>>(out);
}

// round 6
// speedup vs baseline: 2.3781x; 1.3727x over previous
#include <cuda_runtime.h>
#include <cuda_bf16.h>
#include <math.h>
#include <stdint.h>

// Problem dims (fixed by setup_inputs)
#define NB 8
#define NS 2048
#define DV 768
#define DA 512
#define NK 512
#define NR (NB*NS)            // 16384 rows
#define LAM 0.3f

// Fused GEMM tiling (mma.sync m16n8k16 bf16)
#define BM 128
#define BN 128
#define BK 32                 // bf16 k per chunk
#define NTH 256
#define LDSE 40               // smem row stride in bf16 elements (80 bytes)
#define ATILE 10240           // 128 rows * 80 B
#define STGB 20480            // one stage: A tile + B tile
#define NSTAGE 3
#define FUSED_SMEM (NSTAGE*STGB)   // 61440
#define NBLOCKS ((NK/BN)*(NR/BM)*2)   // 1024

// ---------------- device scratch; bf16 stored in uint4 arrays (16B-aligned) --
__device__ uint4 g_fV16u[(size_t)NR*DV/8];   // bf16 feat_vision
__device__ uint4 g_fA16u[(size_t)NR*DA/8];
__device__ uint4 g_sV16u[(size_t)NR*DV/8];   // bf16 smooth(feat_vision)
__device__ uint4 g_sA16u[(size_t)NR*DA/8];
__device__ uint4 g_pV16u[NK*DV/8];           // bf16 proto_vision
__device__ uint4 g_pA16u[NK*DA/8];
__device__ uint4 g_Mv16u[NK*DA/8];           // bf16 proto_v @ W_a2v
__device__ uint4 g_Ma16u[NK*DV/8];
__device__ float g_Mv[NK*DA];                // fp32 M (validated producer)
__device__ float g_Ma[NK*DV];
__device__ float g_partials[NBLOCKS];

#define G_FV16 ((__nv_bfloat16*)g_fV16u)
#define G_FA16 ((__nv_bfloat16*)g_fA16u)
#define G_SV16 ((__nv_bfloat16*)g_sV16u)
#define G_SA16 ((__nv_bfloat16*)g_sA16u)
#define G_PV16 ((__nv_bfloat16*)g_pV16u)
#define G_PA16 ((__nv_bfloat16*)g_pA16u)
#define G_MV16 ((__nv_bfloat16*)g_Mv16u)
#define G_MA16 ((__nv_bfloat16*)g_Ma16u)

// ---------------- helpers ----------------
__device__ __forceinline__ uint32_t smem_u32(const void* p) {
    uint32_t a;
    asm("{ .reg .u64 t; cvta.to.shared.u64 t, %1; cvt.u32.u64 %0, t; }" : "=r"(a) : "l"(p));
    return a;
}
__device__ __forceinline__ void cp16(uint32_t dst, const void* src) {
    asm volatile("cp.async.cg.shared.global [%0], [%1], 16;" :: "r"(dst), "l"(src) : "memory");
}
__device__ __forceinline__ void cp_commit() {
    asm volatile("cp.async.commit_group;" ::: "memory");
}
__device__ __forceinline__ void ldsm4(uint32_t* r, uint32_t addr) {
    asm volatile("ldmatrix.sync.aligned.m8n8.x4.shared.b16 {%0,%1,%2,%3}, [%4];"
                 : "=r"(r[0]), "=r"(r[1]), "=r"(r[2]), "=r"(r[3]) : "r"(addr));
}
__device__ __forceinline__ void ldsm2(uint32_t* r, uint32_t addr) {
    asm volatile("ldmatrix.sync.aligned.m8n8.x2.shared.b16 {%0,%1}, [%2];"
                 : "=r"(r[0]), "=r"(r[1]) : "r"(addr));
}
__device__ __forceinline__ void mma16816(float* c, const uint32_t* a, const uint32_t* b) {
    asm volatile(
        "mma.sync.aligned.m16n8k16.row.col.f32.bf16.bf16.f32 "
        "{%0,%1,%2,%3}, {%4,%5,%6,%7}, {%8,%9}, {%0,%1,%2,%3};"
        : "+f"(c[0]), "+f"(c[1]), "+f"(c[2]), "+f"(c[3])
        : "r"(a[0]), "r"(a[1]), "r"(a[2]), "r"(a[3]), "r"(b[0]), "r"(b[1]));
}
__device__ __forceinline__ uint2 cvt4(float4 v) {
    __nv_bfloat162 lo = __floats2bfloat162_rn(v.x, v.y);
    __nv_bfloat162 hi = __floats2bfloat162_rn(v.z, v.w);
    uint2 r;
    r.x = *reinterpret_cast<uint32_t*>(&lo);
    r.y = *reinterpret_cast<uint32_t*>(&hi);
    return r;
}

// ---------------------------------------------------------------------------
// R1-VALIDATED smooth computation + trivial bf16 dual store (smooth + feat).
// which=1 -> vision, which=0 -> audio
// ---------------------------------------------------------------------------
__global__ void smooth_cvt2_kernel(const float* __restrict__ f, int D, int which)
{
    uint2* __restrict__ s16 = reinterpret_cast<uint2*>(which ? G_SV16 : G_SA16);
    uint2* __restrict__ f16 = reinterpret_cast<uint2*>(which ? G_FV16 : G_FA16);
    const float4* __restrict__ fv = reinterpret_cast<const float4*>(f);
    const int D4 = D >> 2;
    const long total = (long)NR * D4;
    const float inv3 = 1.0f / 3.0f;
    for (long i = (long)blockIdx.x*blockDim.x + threadIdx.x; i < total;
         i += (long)gridDim.x*blockDim.x) {
        long row = i / D4;
        int s = (int)(row % NS);
        float4 c = fv[i];
        float4 r;
        if (s == 0) {
            float4 n = fv[i + D4];
            r.x=(c.x+n.x)*0.5f; r.y=(c.y+n.y)*0.5f;
            r.z=(c.z+n.z)*0.5f; r.w=(c.w+n.w)*0.5f;
        } else if (s == NS-1) {
            float4 p = fv[i - D4];
            r.x=(c.x+p.x)*0.5f; r.y=(c.y+p.y)*0.5f;
            r.z=(c.z+p.z)*0.5f; r.w=(c.w+p.w)*0.5f;
        } else {
            float4 p = fv[i - D4];
            float4 n = fv[i + D4];
            r.x=(p.x+c.x+n.x)*inv3; r.y=(p.y+c.y+n.y)*inv3;
            r.z=(p.z+c.z+n.z)*inv3; r.w=(p.w+c.w+n.w)*inv3;
        }
        s16[i] = cvt4(r);
        f16[i] = cvt4(c);
    }
}

// ---------------------------------------------------------------------------
// R1-VALIDATED: M = P @ W (fp32), 16x16 tiles. which=0 -> g_Mv, 1 -> g_Ma
// ---------------------------------------------------------------------------
__global__ void proto_proj_kernel(const float* __restrict__ P,
                                  const float* __restrict__ W,
                                  int D, int C, int which)
{
    float* __restrict__ Cout = which ? g_Ma : g_Mv;
    __shared__ float As[16][16];
    __shared__ float Ws[16][17];
    int tx = threadIdx.x, ty = threadIdx.y;
    int row = blockIdx.y*16 + ty;
    int col = blockIdx.x*16 + tx;
    float acc = 0.f;
    for (int d0 = 0; d0 < D; d0 += 16) {
        As[ty][tx] = P[row*D + d0 + tx];
        Ws[ty][tx] = W[(d0+ty)*C + col];
        __syncthreads();
        #pragma unroll
        for (int kk = 0; kk < 16; kk++) acc += As[ty][kk]*Ws[kk][tx];
        __syncthreads();
    }
    Cout[row*C + col] = acc;
}

// ---------------------------------------------------------------------------
// Trivial scalar fp32 -> bf16. which: 0->pV16, 1->pA16, 2->Mv16, 3->Ma16
// ---------------------------------------------------------------------------
__global__ void cvt_scalar_kernel(const float* __restrict__ in, int n, int which)
{
    __nv_bfloat16* dst = (which == 0) ? G_PV16 : (which == 1) ? G_PA16
                       : (which == 2) ? G_MV16 : G_MA16;
    for (int i = blockIdx.x*blockDim.x + threadIdx.x; i < n; i += gridDim.x*blockDim.x) {
        float v = (which < 2) ? in[i] : (which == 2 ? g_Mv[i] : g_Ma[i]);
        dst[i] = __float2bfloat16(v);
    }
}

// ---------------------------------------------------------------------------
// Fused HMMA energy kernel. gridDim = (NK/BN, NR/BM, 2 modalities).
// bf16 gmem sources, 3-stage cp.async pipeline (1 barrier per chunk),
// ldmatrix fragment loads (proven equivalent to validated direct-LDS core).
// ---------------------------------------------------------------------------
extern __shared__ char dsm[];

__global__ __launch_bounds__(NTH, 1)
void fused_energy_kernel()
{
    __shared__ float red_s[8];

    const int tid = threadIdx.x;
    const int wid = tid >> 5;
    const int lane = tid & 31;
    const int z = blockIdx.z;
    const long row0 = (long)blockIdx.y * BM;
    const long col0 = (long)blockIdx.x * BN;

    const __nv_bfloat16 *A1, *B1, *A2, *B2;
    int D1, D2;
    if (z == 0) { A1 = G_FV16; B1 = G_PV16; D1 = DV; A2 = G_SA16; B2 = G_MV16; D2 = DA; }
    else        { A1 = G_FA16; B1 = G_PA16; D1 = DA; A2 = G_SV16; B2 = G_MA16; D2 = DV; }
    const int n1 = D1 / BK;
    const int nch = n1 + D2 / BK;

    const uint32_t base0 = smem_u32(dsm);

    auto load_chunk = [&](int c, int stage) {
        const __nv_bfloat16 *A, *B; int D, k0;
        if (c < n1) { A = A1; B = B1; D = D1; k0 = c * BK; }
        else        { A = A2; B = B2; D = D2; k0 = (c - n1) * BK; }
        uint32_t base = base0 + stage * STGB;
        #pragma unroll
        for (int r = 0; r < 2; r++) {
            int u = tid + r * 256;       // 512 units of 16B per tile
            int row = u >> 2, seg = u & 3;
            uint32_t d = base + (uint32_t)(row * 80 + seg * 16);
            cp16(d,         A + (row0 + row) * D + k0 + seg * 8);
            cp16(d + ATILE, B + (col0 + row) * D + k0 + seg * 8);
        }
        cp_commit();
    };

    const int wm = (wid >> 2) * 64;   // warp row base
    const int wn = (wid & 3) * 32;    // warp col base
    const int arow = wm + (lane & 7) + ((lane >> 3) & 1) * 8;
    const int acol = (lane >> 4) * 16;           // byte offset (k-half)
    const int l2 = lane & 15;
    const int brow = wn + (l2 & 7);
    const int bcol = ((l2 >> 3) & 1) * 16;

    auto compute_chunk = [&](int stage, float (*acc)[4][4]) {
        uint32_t sA = base0 + stage * STGB;
        uint32_t sB = sA + ATILE;
        #pragma unroll
        for (int ks = 0; ks < 2; ks++) {
            uint32_t a[4][4];
            #pragma unroll
            for (int i = 0; i < 4; i++)
                ldsm4(a[i], sA + (uint32_t)((arow + i * 16) * 80 + acol + ks * 32));
            uint32_t b[4][2];
            #pragma unroll
            for (int j = 0; j < 4; j++)
                ldsm2(b[j], sB + (uint32_t)((brow + j * 8) * 80 + bcol + ks * 32));
            #pragma unroll
            for (int i = 0; i < 4; i++)
                #pragma unroll
                for (int j = 0; j < 4; j++)
                    mma16816(acc[i][j], a[i], b[j]);
        }
    };

    float acc1[4][4][4] = {};
    float acc2[4][4][4] = {};

    load_chunk(0, 0);
    load_chunk(1, 1);

    for (int c = 0; c < nch; c++) {
        // ensure chunk c landed (it is the oldest outstanding group)
        if (c + 1 < nch) asm volatile("cp.async.wait_group 1;" ::: "memory");
        else             asm volatile("cp.async.wait_group 0;" ::: "memory");
        __syncthreads();   // chunk c visible to all; all warps done with chunk c-1
        if (c + 2 < nch) load_chunk(c + 2, (c + 2) % NSTAGE);
        compute_chunk(c % NSTAGE, (c < n1) ? acc1 : acc2);
    }

    // Epilogue: elementwise softplus on matching fragments, then reduce.
    float local = 0.f;
    #pragma unroll
    for (int i = 0; i < 4; i++)
        #pragma unroll
        for (int j = 0; j < 4; j++)
            #pragma unroll
            for (int r = 0; r < 4; r++) {
                float c1 = acc1[i][j][r];
                float c2 = acc2[i][j][r];
                float sal = LAM * c2 * c2 + (1.0f - LAM) * c1 * c1;
                float x = sal * c1;
                local += fmaxf(x, 0.f) + log1pf(__expf(-fabsf(x)));
            }
    #pragma unroll
    for (int o = 16; o > 0; o >>= 1)
        local += __shfl_xor_sync(0xFFFFFFFF, local, o);
    if (lane == 0) red_s[wid] = local;
    __syncthreads();
    if (tid == 0) {
        float s = 0.f;
        #pragma unroll
        for (int w = 0; w < 8; w++) s += red_s[w];
        g_partials[(z * gridDim.y + blockIdx.y) * gridDim.x + blockIdx.x] = s;
    }
}

// ---------------------------------------------------------------------------
// Deterministic final reduction
// ---------------------------------------------------------------------------
__global__ void final_reduce_kernel(float* __restrict__ out)
{
    __shared__ double red[256];
    double s = 0.0;
    for (int i = threadIdx.x; i < NBLOCKS; i += 256) s += (double)g_partials[i];
    red[threadIdx.x] = s;
    __syncthreads();
    for (int st = 128; st > 0; st >>= 1) {
        if (threadIdx.x < st) red[threadIdx.x] += red[threadIdx.x + st];
        __syncthreads();
    }
    if (threadIdx.x == 0) out[0] = (float)(-red[0]);
}

// ---------------------------------------------------------------------------
extern "C" void kernel_launch(void* const* d_in, const int* in_sizes, int n_in,
                              void* d_out, int out_size)
{
    const float* fv  = (const float*)d_in[0];   // (8,2048,768)
    const float* fa  = (const float*)d_in[1];   // (8,2048,512)
    const float* pv  = (const float*)d_in[2];   // (512,768)
    const float* pa  = (const float*)d_in[3];   // (512,512)
    const float* wav = (const float*)d_in[4];   // (768,512)
    const float* wva = (const float*)d_in[5];   // (512,768)
    float* out = (float*)d_out;

    cudaFuncSetAttribute(fused_energy_kernel,
                         cudaFuncAttributeMaxDynamicSharedMemorySize, FUSED_SMEM);

    smooth_cvt2_kernel<<<4096, 256>>>(fv, DV, 1);   // bf16 smooth + feat (vision)
    smooth_cvt2_kernel<<<4096, 256>>>(fa, DA, 0);   // bf16 smooth + feat (audio)

    proto_proj_kernel<<<dim3(DA/16, NK/16), dim3(16,16)>>>(pv, wav, DV, DA, 0);  // g_Mv
    proto_proj_kernel<<<dim3(DV/16, NK/16), dim3(16,16)>>>(pa, wva, DA, DV, 1);  // g_Ma

    cvt_scalar_kernel<<<512, 256>>>(pv, NK*DV, 0);
    cvt_scalar_kernel<<<512, 256>>>(pa, NK*DA, 1);
    cvt_scalar_kernel<<<512, 256>>>(nullptr, NK*DA, 2);
    cvt_scalar_kernel<<<512, 256>>>(nullptr, NK*DV, 3);

    fused_energy_kernel<<<dim3(NK/BN, NR/BM, 2), NTH, FUSED_SMEM>>>();

    final_reduce_kernel<<<1, 256>>>(out);
}